// round 12
// baseline (speedup 1.0000x reference)
#include <cuda_runtime.h>
#include <math.h>

// YOLOv1 loss — single launch, register-streaming variant.
// R11 held 48KB smem (full tensors staged) -> 4 CTAs/SM -> staging and
// compute phases alternated with memory idle during compute (DRAM 37%).
// This version streams class channels through registers (read-once) and
// stages only the revisited data: per-cell t4 + box channels (17KB smem)
// -> ~2.5x more CTAs/SM, desynchronized phases, continuous memory traffic.
//
// Exactness: max_iou is only ever compared against 0, and union>0 always
// (w,h >= 0.05), so cmask == "exists masked pred box with intersection > 0".
// The intersection arithmetic (cx - 0.5f*w, min/max/sub, >0 test) matches the
// reference ops exactly, so the decision is bit-identical.
//
// Graph-replay invariants: g_partCTA fully overwritten each run; g_count is 0
// at the start of every launch (reset by the last CTA after use).

#define CELLS 49
#define CH 30
#define FPS (CELLS * CH)          // 1470 floats per sample
#define SPC 4                     // samples per CTA
#define TPB 128                   // 4 warps, one per sample
#define CCELLS (SPC * CELLS)      // 196 cells per CTA
#define MAXB 8192
#define MAXCTA ((MAXB + SPC - 1) / SPC)

__device__ __align__(16) float4 g_partCTA[MAXCTA];  // per-CTA {noobj, cls, coord, objc}
__device__ unsigned int g_count = 0;

__global__ __launch_bounds__(TPB, 10) void yolo_fused_kernel(
    const float* __restrict__ pred, const float* __restrict__ target,
    float* __restrict__ out, int B, int total_floats, int ncta)
{
    __shared__ float sbox[CCELLS * 20];   // per cell: pred ch0-9 | target ch0-9
    __shared__ float st4s[CCELLS];        // per cell: target conf (exactly 0/1)
    __shared__ int s_list[SPC][CELLS];
    __shared__ float4 s_red[4];
    __shared__ int s_last;

    const int tid  = threadIdx.x;
    const int lane = tid & 31;
    const int w    = tid >> 5;                      // warp == sample-in-CTA
    const int f0   = blockIdx.x * (SPC * FPS);      // CTA base float (16B aligned)
    const int flen = min(SPC * FPS, total_floats - f0);
    const int ncells_cta = flen / CH;               // full cells in this CTA

    // ---- t4 preload (also warms L2 for the stream) ----
    for (int c = tid; c < ncells_cta; c += TPB)
        st4s[c] = target[f0 + c * CH + 4];
    __syncthreads();

    float cls = 0.f;

    // ---- register streaming: class terms on the fly, boxes scattered to smem ----
    {
        const float4* gp4 = (const float4*)(pred + f0);
        const float4* gt4 = (const float4*)(target + f0);
        const int nv4 = flen >> 2;
        #pragma unroll 2
        for (int i = tid; i < nv4; i += TPB) {
            const float4 p = gp4[i];
            const float4 t = gt4[i];
            const int f = 4 * i;
            const float pv[4] = {p.x, p.y, p.z, p.w};
            const float tv[4] = {t.x, t.y, t.z, t.w};
            #pragma unroll
            for (int e = 0; e < 4; e++) {
                const unsigned ff = (unsigned)(f + e);
                const unsigned cell = ff / 30u;       // mul-shift
                const int ch = (int)(ff - cell * 30u);
                if (ch < 10) {
                    sbox[cell * 20 + ch]      = pv[e];
                    sbox[cell * 20 + 10 + ch] = tv[e];
                } else if (st4s[cell] != 0.f) {
                    const float d = pv[e] - tv[e];
                    cls += d * d;
                }
            }
        }
        // scalar tail (only when flen not a multiple of 4: partial last CTA)
        for (int ff = (nv4 << 2) + tid; ff < flen; ff += TPB) {
            const unsigned cell = (unsigned)ff / 30u;
            const int ch = ff - (int)cell * 30;
            const float pv = pred[f0 + ff];
            const float tv = target[f0 + ff];
            if (ch < 10) {
                sbox[cell * 20 + ch]      = pv;
                sbox[cell * 20 + 10 + ch] = tv;
            } else if (st4s[cell] != 0.f) {
                const float d = pv - tv;
                cls += d * d;
            }
        }
    }
    __syncthreads();

    const int s = blockIdx.x * SPC + w;             // global sample of this warp
    float noobj = 0.f, coord = 0.f, objc = 0.f;

    if (s < B) {
        // ---- phase 1: noobj terms + ballot compaction of obj cells ----
        int nobj = 0;
        #pragma unroll
        for (int half = 0; half < 2; half++) {
            const int c = lane + 32 * half;
            bool isobj = false;
            if (c < CELLS) {
                const int cc = w * CELLS + c;
                const float* rec = sbox + cc * 20;
                if (st4s[cc] == 0.f) {
                    const float d4 = rec[4] - rec[14];
                    const float d9 = rec[9] - rec[19];
                    noobj += d4 * d4 + d9 * d9;
                } else {
                    isobj = true;
                }
            }
            const unsigned m = __ballot_sync(0xffffffffu, isobj);
            if (isobj)
                s_list[w][nobj + __popc(m & ((1u << lane) - 1u))] = w * CELLS + c;
            nobj += __popc(m);
        }
        __syncwarp();

        // ---- phase 2: in-warp pairing (existence test with early exit) ----
        const int nbox = 2 * nobj;
        for (int i = lane; i < nbox; i += 32) {
            const int cc = s_list[w][i >> 1];
            const int po_t = cc * 20 + 10 + 5 * (i & 1);   // target box i
            const float tcx = sbox[po_t],     tcy = sbox[po_t + 1];
            const float tw  = sbox[po_t + 2], th  = sbox[po_t + 3];
            const float tx0 = tcx - 0.5f * tw, ty0 = tcy - 0.5f * th;
            const float tx1 = tcx + 0.5f * tw, ty1 = tcy + 0.5f * th;

            bool found = false;
            for (int j = 0; j < nbox; j++) {               // j uniform -> LDS broadcast
                const int po = s_list[w][j >> 1] * 20 + 5 * (j & 1);  // pred box j
                const float pcx = sbox[po],     pcy = sbox[po + 1];
                const float pw  = sbox[po + 2], ph  = sbox[po + 3];
                const float ix = fminf(pcx + 0.5f * pw, tx1) - fmaxf(pcx - 0.5f * pw, tx0);
                const float iy = fminf(pcy + 0.5f * ph, ty1) - fmaxf(pcy - 0.5f * ph, ty0);
                if (ix > 0.f && iy > 0.f && ix * iy > 0.f) { found = true; break; }
            }
            if (found) {
                const int po_p = cc * 20 + 5 * (i & 1);    // pred box i
                const float dx = sbox[po_p]     - tcx;
                const float dy = sbox[po_p + 1] - tcy;
                const float dw = sqrtf(sbox[po_p + 2]) - sqrtf(tw);
                const float dh = sqrtf(sbox[po_p + 3]) - sqrtf(th);
                coord += dx * dx + dy * dy + dw * dw + dh * dh;
                const float dc = sbox[po_p + 4] - sbox[po_t + 4];
                objc += dc * dc;
            }
        }
    }

    // ---- warp reduce, then CTA combine to one float4 ----
    #pragma unroll
    for (int o = 16; o > 0; o >>= 1) {
        noobj += __shfl_down_sync(0xffffffffu, noobj, o);
        cls   += __shfl_down_sync(0xffffffffu, cls, o);
        coord += __shfl_down_sync(0xffffffffu, coord, o);
        objc  += __shfl_down_sync(0xffffffffu, objc, o);
    }
    if (lane == 0)
        s_red[w] = make_float4(noobj, cls, coord, objc);
    __syncthreads();

    if (tid == 0) {
        float4 r = s_red[0];
        #pragma unroll
        for (int k = 1; k < 4; k++) {
            r.x += s_red[k].x; r.y += s_red[k].y;
            r.z += s_red[k].z; r.w += s_red[k].w;
        }
        g_partCTA[blockIdx.x] = r;
        __threadfence();
        const unsigned int old = atomicAdd(&g_count, 1u);
        s_last = (old == (unsigned int)(ncta - 1)) ? 1 : 0;
    }
    __syncthreads();

    if (!s_last) return;

    // ---- last CTA: final reduction over ncta float4 (L2-hot, fixed order) ----
    double a0 = 0.0, a1 = 0.0, a2 = 0.0, a3 = 0.0;
    for (int i = tid; i < ncta; i += TPB) {
        const float4 v = g_partCTA[i];
        a0 += (double)v.x;
        a1 += (double)v.y;
        a2 += (double)v.z;
        a3 += (double)v.w;
    }
    #pragma unroll
    for (int o = 16; o > 0; o >>= 1) {
        a0 += __shfl_down_sync(0xffffffffu, a0, o);
        a1 += __shfl_down_sync(0xffffffffu, a1, o);
        a2 += __shfl_down_sync(0xffffffffu, a2, o);
        a3 += __shfl_down_sync(0xffffffffu, a3, o);
    }
    __shared__ double sd[4][4];
    if (lane == 0) { sd[0][w] = a0; sd[1][w] = a1; sd[2][w] = a2; sd[3][w] = a3; }
    __syncthreads();
    if (tid == 0) {
        double r0 = 0, r1 = 0, r2 = 0, r3 = 0;
        #pragma unroll
        for (int k = 0; k < 4; k++) {
            r0 += sd[0][k]; r1 += sd[1][k]; r2 += sd[2][k]; r3 += sd[3][k];
        }
        const double inv = 1.0 / (double)B;
        const double cls_l = r1 * inv;
        const double obj_l = (r3 + 0.5 * r0) * inv;
        const double crd_l = r2 * 5.0 * inv;
        out[0] = (float)(cls_l + obj_l + crd_l);
        out[1] = (float)cls_l;
        out[2] = (float)obj_l;
        out[3] = (float)crd_l;
        g_count = 0u;                               // restore replay invariant
    }
}

extern "C" void kernel_launch(void* const* d_in, const int* in_sizes, int n_in,
                              void* d_out, int out_size)
{
    const float* pred = (const float*)d_in[0];
    const float* target = (const float*)d_in[1];
    const int B = in_sizes[0] / FPS;
    const int total_floats = B * FPS;
    const int ncta = (B + SPC - 1) / SPC;

    yolo_fused_kernel<<<ncta, TPB>>>(pred, target, (float*)d_out, B, total_floats, ncta);
}

// round 13
// speedup vs baseline: 1.1996x; 1.1996x over previous
#include <cuda_runtime.h>
#include <math.h>

// YOLOv1 loss — gather variant: read only the bytes the loss uses.
// noobj cells (~80%) need 4 floats of 60; obj cells need all 60. A warp-per-
// sample gather cuts sector traffic ~96MB -> ~64MB and removes all staging
// barriers: no cp.async, no CTA-wide sync until the final reduce, 8192
// independent warps with ~16 independent loads per lane.
//
// Exactness: max_iou is only ever compared against 0, and union>0 always
// (w,h >= 0.05), so cmask == "exists masked pred box with intersection > 0".
// The intersection arithmetic (cx - 0.5f*w, min/max/sub, >0 test) matches the
// reference ops exactly, so the decision is bit-identical. For noobj cells
// t4 == 0.0f exactly, so d4 = p4 - 0.0f = p4 exactly.
//
// Graph-replay invariants: g_partCTA fully overwritten each run; g_count is 0
// at the start of every launch (reset by the last CTA after use).

#define CELLS 49
#define CH 30
#define FPS (CELLS * CH)          // 1470 floats per sample
#define WPB 8                     // warps (samples) per CTA
#define TPB (32 * WPB)            // 256 threads
#define MAXB 8192
#define MAXCTA ((MAXB + WPB - 1) / WPB)

__device__ __align__(16) float4 g_partCTA[MAXCTA];  // per-CTA {noobj, cls, coord, objc}
__device__ unsigned int g_count = 0;

__global__ __launch_bounds__(TPB) void yolo_gather_kernel(
    const float* __restrict__ pred, const float* __restrict__ target,
    float* __restrict__ out, int B, int ncta)
{
    // box records indexed by COMPACT obj index k: [0..9]=pred ch0-9, [10..19]=target ch0-9
    __shared__ float sbox[WPB][CELLS * 20];
    __shared__ int   s_list[WPB][CELLS];
    __shared__ float4 s_red[WPB];
    __shared__ int s_last;

    const int tid  = threadIdx.x;
    const int lane = tid & 31;
    const int w    = tid >> 5;
    const int s    = blockIdx.x * WPB + w;          // sample owned by this warp

    float noobj = 0.f, cls = 0.f, coord = 0.f, objc = 0.f;

    if (s < B) {
        const float* bp = pred + (size_t)s * FPS;
        const float* bt = target + (size_t)s * FPS;

        // ---- phase A: conf gather, noobj terms, obj-cell compaction ----
        int nobj = 0;
        #pragma unroll
        for (int half = 0; half < 2; half++) {
            const int c = lane + 32 * half;
            bool isobj = false;
            if (c < CELLS) {
                const int o = c * CH;
                const float t4 = bt[o + 4];         // exactly 0.0 or 1.0
                const float p4 = bp[o + 4];
                const float p9 = bp[o + 9];
                const float t9 = bt[o + 9];
                if (t4 == 0.f) {
                    const float d9 = p9 - t9;
                    noobj += p4 * p4 + d9 * d9;     // d4 = p4 - 0 = p4 exactly
                } else {
                    isobj = true;
                }
            }
            const unsigned m = __ballot_sync(0xffffffffu, isobj);
            if (isobj)
                s_list[w][nobj + __popc(m & ((1u << lane) - 1u))] = c;
            nobj += __popc(m);
        }
        __syncwarp();

        // ---- phase B: gather obj-cell boxes (ch0-9 both tensors) to smem ----
        // work item e: obj index k = e/10, f2 = e%10; f2<5 -> pred pair, else target
        const int nitems = nobj * 10;
        for (int e = lane; e < nitems; e += 32) {
            const int k  = e / 10;
            const int f2 = e % 10;
            const int m5 = (f2 >= 5) ? f2 - 5 : f2;
            const int c  = s_list[w][k];
            const int o  = c * CH + 2 * m5;         // even offset -> float2 safe
            const float2 v = (f2 < 5) ? *(const float2*)(bp + o)
                                      : *(const float2*)(bt + o);
            float* rec = &sbox[w][k * 20 + ((f2 < 5) ? 0 : 10) + 2 * m5];
            rec[0] = v.x;
            rec[1] = v.y;
        }

        // ---- phase C: class loss for obj cells (ch10-29, float2 pairs) ----
        for (int e = lane; e < nitems; e += 32) {   // nobj*10 float2 positions
            const int k = e / 10;
            const int m = e % 10;
            const int o = s_list[w][k] * CH + 10 + 2 * m;
            const float2 pv = *(const float2*)(bp + o);
            const float2 tv = *(const float2*)(bt + o);
            const float dx = pv.x - tv.x;
            const float dy = pv.y - tv.y;
            cls += dx * dx + dy * dy;
        }
        __syncwarp();                               // sbox writes visible in-warp

        // ---- phase D: pairing (existence test with early exit) ----
        const int nbox = 2 * nobj;
        const float* base = sbox[w];
        for (int i = lane; i < nbox; i += 32) {
            const int rt = (i >> 1) * 20 + 10 + 5 * (i & 1);   // target box i
            const float tcx = base[rt],     tcy = base[rt + 1];
            const float tw  = base[rt + 2], th  = base[rt + 3];
            const float tx0 = tcx - 0.5f * tw, ty0 = tcy - 0.5f * th;
            const float tx1 = tcx + 0.5f * tw, ty1 = tcy + 0.5f * th;

            bool found = false;
            for (int j = 0; j < nbox; j++) {        // j uniform -> LDS broadcast
                const int rp = (j >> 1) * 20 + 5 * (j & 1);    // pred box j
                const float pcx = base[rp],     pcy = base[rp + 1];
                const float pw  = base[rp + 2], ph  = base[rp + 3];
                const float ix = fminf(pcx + 0.5f * pw, tx1) - fmaxf(pcx - 0.5f * pw, tx0);
                const float iy = fminf(pcy + 0.5f * ph, ty1) - fmaxf(pcy - 0.5f * ph, ty0);
                if (ix > 0.f && iy > 0.f && ix * iy > 0.f) { found = true; break; }
            }
            if (found) {
                const int rp = (i >> 1) * 20 + 5 * (i & 1);    // pred box i
                const float dx = base[rp]     - tcx;
                const float dy = base[rp + 1] - tcy;
                const float dw = sqrtf(base[rp + 2]) - sqrtf(tw);
                const float dh = sqrtf(base[rp + 3]) - sqrtf(th);
                coord += dx * dx + dy * dy + dw * dw + dh * dh;
                const float dc = base[rp + 4] - base[rt + 4];
                objc += dc * dc;
            }
        }
    }

    // ---- warp reduce, CTA combine, last-CTA finish ----
    #pragma unroll
    for (int o = 16; o > 0; o >>= 1) {
        noobj += __shfl_down_sync(0xffffffffu, noobj, o);
        cls   += __shfl_down_sync(0xffffffffu, cls, o);
        coord += __shfl_down_sync(0xffffffffu, coord, o);
        objc  += __shfl_down_sync(0xffffffffu, objc, o);
    }
    if (lane == 0)
        s_red[w] = make_float4(noobj, cls, coord, objc);
    __syncthreads();

    if (tid == 0) {
        float4 r = s_red[0];
        #pragma unroll
        for (int k = 1; k < WPB; k++) {
            r.x += s_red[k].x; r.y += s_red[k].y;
            r.z += s_red[k].z; r.w += s_red[k].w;
        }
        g_partCTA[blockIdx.x] = r;
        __threadfence();
        const unsigned int old = atomicAdd(&g_count, 1u);
        s_last = (old == (unsigned int)(ncta - 1)) ? 1 : 0;
    }
    __syncthreads();

    if (!s_last) return;

    // ---- last CTA: final reduction over ncta float4 (L2-hot, fixed order) ----
    double a0 = 0.0, a1 = 0.0, a2 = 0.0, a3 = 0.0;
    for (int i = tid; i < ncta; i += TPB) {
        const float4 v = g_partCTA[i];
        a0 += (double)v.x;
        a1 += (double)v.y;
        a2 += (double)v.z;
        a3 += (double)v.w;
    }
    #pragma unroll
    for (int o = 16; o > 0; o >>= 1) {
        a0 += __shfl_down_sync(0xffffffffu, a0, o);
        a1 += __shfl_down_sync(0xffffffffu, a1, o);
        a2 += __shfl_down_sync(0xffffffffu, a2, o);
        a3 += __shfl_down_sync(0xffffffffu, a3, o);
    }
    __shared__ double sd[4][WPB];
    if (lane == 0) { sd[0][w] = a0; sd[1][w] = a1; sd[2][w] = a2; sd[3][w] = a3; }
    __syncthreads();
    if (tid == 0) {
        double r0 = 0, r1 = 0, r2 = 0, r3 = 0;
        #pragma unroll
        for (int k = 0; k < WPB; k++) {
            r0 += sd[0][k]; r1 += sd[1][k]; r2 += sd[2][k]; r3 += sd[3][k];
        }
        const double inv = 1.0 / (double)B;
        const double cls_l = r1 * inv;
        const double obj_l = (r3 + 0.5 * r0) * inv;
        const double crd_l = r2 * 5.0 * inv;
        out[0] = (float)(cls_l + obj_l + crd_l);
        out[1] = (float)cls_l;
        out[2] = (float)obj_l;
        out[3] = (float)crd_l;
        g_count = 0u;                               // restore replay invariant
    }
}

extern "C" void kernel_launch(void* const* d_in, const int* in_sizes, int n_in,
                              void* d_out, int out_size)
{
    const float* pred = (const float*)d_in[0];
    const float* target = (const float*)d_in[1];
    const int B = in_sizes[0] / FPS;
    const int ncta = (B + WPB - 1) / WPB;

    yolo_gather_kernel<<<ncta, TPB>>>(pred, target, (float*)d_out, B, ncta);
}